// round 16
// baseline (speedup 1.0000x reference)
#include <cuda_runtime.h>
#include <cstdint>

// Problem constants
#define NB   16
#define NL   128
#define NE   300
#define NH   512
#define NT   9
#define NBIOE 64
#define NREL 128
#define NR   50

// ---------------- scratch layout (floats) ----------------
#define EMB_OFF    0            // 2048*300
#define BSUM_OFF   1228800      // 2*2048
#define XP_OFF     1232896      // 2 * 2048*2048
#define HS_OFF     9621504      // 2 * 128*16*512
#define EMI_OFF    12783616     // 2048*9
#define OC_OFF     12802048     // 2048*576
#define U_OFF      13981696     // 2048*128
#define V_OFF      14243840     // 2048*128
#define U1_OFF     14505984     // 2048*128
#define V2_OFF     14768128     // 2048*128
#define MASKF_OFF  15030272     // 2048
#define SCRATCH_SZ 15032320

__device__ __align__(16) float g_scratch[SCRATCH_SZ];
__device__ double g_sel_sum;
__device__ int    g_mask_count;
__device__ float  g_crf_loss;
// per-block step flags: [dir][slice], each on its own 128B line
__device__ unsigned g_flags[2][64][32];

__device__ __forceinline__ float sigm(float x) { return 1.f / (1.f + expf(-x)); }

#define FMA_F32X2(d, a, b) \
    asm("fma.rn.f32x2 %0, %1, %2, %0;" : "+l"(d) : "l"(a), "l"(b))

// ---------------- prep: embed gather + mask, bias sums, accumulator zeroing --
__global__ void prep_kernel(const int* __restrict__ tokens,
                            const float* __restrict__ wemb,
                            const float* bif, const float* bhf,
                            const float* bib, const float* bhb) {
    int bx = blockIdx.x, tid = threadIdx.x;
    if (bx < 2400) {
        int idx = bx * 256 + tid;                  // < 2048*300
        int bl = idx / NE;
        int e  = idx - bl * NE;
        int tok = tokens[bl];
        g_scratch[EMB_OFF + idx] = wemb[(size_t)tok * NE + e];
        if (e == 0) g_scratch[MASKF_OFF + bl] = (tok != 0) ? 1.f : 0.f;
    } else if (bx < 2416) {
        int idx = (bx - 2400) * 256 + tid;         // < 4096
        int d = idx >> 11, g = idx & 2047;
        g_scratch[BSUM_OFF + idx] = d ? (bib[g] + bhb[g]) : (bif[g] + bhf[g]);
    } else {
        if (tid == 0) {
            g_sel_sum = 0.0;
            g_mask_count = 0;
            g_crf_loss = 0.f;
        }
        if (tid < 128) g_flags[tid >> 6][tid & 63][0] = 0u;
    }
}

// ---------------- fused xproj GEMM (proven: 125us) ---------------------------
#define KTILE 16
__global__ __launch_bounds__(256) void xproj_gemm(
    const float* __restrict__ wf, const float* __restrict__ wb)
{
    __shared__ float As[KTILE][132];
    __shared__ float Bs[KTILE][68];
    int tid = threadIdx.x;
    int tx = tid & 15, ty = tid >> 4;
    int rowBase = blockIdx.y * 128;
    int colBase = blockIdx.x * 64;
    int dir = colBase >> 11;
    const float* Bmat = dir ? wb : wf;
    int gcol0 = colBase & 2047;

    float acc[8][4];
#pragma unroll
    for (int i = 0; i < 8; i++)
#pragma unroll
        for (int j = 0; j < 4; j++) acc[i][j] = 0.f;

    for (int k0 = 0; k0 < NE; k0 += KTILE) {
#pragma unroll
        for (int i = 0; i < 2; i++) {
            int f = tid + i * 256;
            int r = f >> 2, kq = f & 3;
            int gk = k0 + kq * 4;
            float4 v = make_float4(0.f, 0.f, 0.f, 0.f);
            if (gk < NE)
                v = *reinterpret_cast<const float4*>(
                        &g_scratch[EMB_OFF + (size_t)(rowBase + r) * NE + gk]);
            As[kq * 4 + 0][r] = v.x;
            As[kq * 4 + 1][r] = v.y;
            As[kq * 4 + 2][r] = v.z;
            As[kq * 4 + 3][r] = v.w;
        }
        {
            int n = tid >> 2, kq = tid & 3;
            int gk = k0 + kq * 4;
            float4 v = make_float4(0.f, 0.f, 0.f, 0.f);
            if (gk < NE)
                v = *reinterpret_cast<const float4*>(
                        &Bmat[(size_t)(gcol0 + n) * NE + gk]);
            Bs[kq * 4 + 0][n] = v.x;
            Bs[kq * 4 + 1][n] = v.y;
            Bs[kq * 4 + 2][n] = v.z;
            Bs[kq * 4 + 3][n] = v.w;
        }
        __syncthreads();
#pragma unroll
        for (int k = 0; k < KTILE; k++) {
            float4 a0 = *reinterpret_cast<const float4*>(&As[k][ty * 8]);
            float4 a1 = *reinterpret_cast<const float4*>(&As[k][ty * 8 + 4]);
            float4 bq = *reinterpret_cast<const float4*>(&Bs[k][tx * 4]);
            acc[0][0] += a0.x * bq.x; acc[0][1] += a0.x * bq.y; acc[0][2] += a0.x * bq.z; acc[0][3] += a0.x * bq.w;
            acc[1][0] += a0.y * bq.x; acc[1][1] += a0.y * bq.y; acc[1][2] += a0.y * bq.z; acc[1][3] += a0.y * bq.w;
            acc[2][0] += a0.z * bq.x; acc[2][1] += a0.z * bq.y; acc[2][2] += a0.z * bq.z; acc[2][3] += a0.z * bq.w;
            acc[3][0] += a0.w * bq.x; acc[3][1] += a0.w * bq.y; acc[3][2] += a0.w * bq.z; acc[3][3] += a0.w * bq.w;
            acc[4][0] += a1.x * bq.x; acc[4][1] += a1.x * bq.y; acc[4][2] += a1.x * bq.z; acc[4][3] += a1.x * bq.w;
            acc[5][0] += a1.y * bq.x; acc[5][1] += a1.y * bq.y; acc[5][2] += a1.y * bq.z; acc[5][3] += a1.y * bq.w;
            acc[6][0] += a1.z * bq.x; acc[6][1] += a1.z * bq.y; acc[6][2] += a1.z * bq.z; acc[6][3] += a1.z * bq.w;
            acc[7][0] += a1.w * bq.x; acc[7][1] += a1.w * bq.y; acc[7][2] += a1.w * bq.z; acc[7][3] += a1.w * bq.w;
        }
        __syncthreads();
    }

    float4 bias = *reinterpret_cast<const float4*>(
        &g_scratch[BSUM_OFF + dir * 2048 + gcol0 + tx * 4]);
    int b = rowBase >> 7;
#pragma unroll
    for (int i = 0; i < 8; i++) {
        int rw = ty * 8 + i;
        int lo = dir ? (127 - rw) : rw;
        float4 v = make_float4(acc[i][0] + bias.x, acc[i][1] + bias.y,
                               acc[i][2] + bias.z, acc[i][3] + bias.w);
        *reinterpret_cast<float4*>(
            &g_scratch[XP_OFF + (size_t)dir * 4194304
                       + (size_t)(b * 128 + lo) * 2048 + gcol0 + tx * 4]) = v;
    }
}

// ---------------- dual NT SGEMM: blockIdx.z picks (A,B,C,bias) set -----------
__global__ __launch_bounds__(256) void sgemm_nt2(
    int a0, int a1, int lda,
    const float* __restrict__ B0, const float* __restrict__ B1, int ldb,
    int c0, int c1, int N, int K,
    const float* __restrict__ bias0, const float* __restrict__ bias1, int relu)
{
    __shared__ float As[64][33];
    __shared__ float Bs[64][33];
    int z = blockIdx.z;
    int aOff = z ? a1 : a0;
    int cOff = z ? c1 : c0;
    const float* Bm = z ? B1 : B0;
    const float* biasExt = z ? bias1 : bias0;

    int tid = threadIdx.x;
    int tx = tid & 15, ty = tid >> 4;
    int rowBase = blockIdx.y * 64;
    int colBase = blockIdx.x * 64;
    const float* A = g_scratch + aOff;

    float acc[4][4];
#pragma unroll
    for (int i = 0; i < 4; i++)
#pragma unroll
        for (int j = 0; j < 4; j++) acc[i][j] = 0.f;

    for (int k0 = 0; k0 < K; k0 += 32) {
#pragma unroll
        for (int i = 0; i < 8; i++) {
            int p = tid + i * 256;
            int r = p >> 5, c = p & 31;
            int gk = k0 + c;
            As[r][c] = (gk < K) ? A[(size_t)(rowBase + r) * lda + gk] : 0.f;
            Bs[r][c] = (gk < K) ? Bm[(size_t)(colBase + r) * ldb + gk] : 0.f;
        }
        __syncthreads();
#pragma unroll
        for (int k = 0; k < 32; k++) {
            float a0v = As[ty * 4 + 0][k], a1v = As[ty * 4 + 1][k];
            float a2v = As[ty * 4 + 2][k], a3v = As[ty * 4 + 3][k];
            float b0 = Bs[tx * 4 + 0][k], b1 = Bs[tx * 4 + 1][k];
            float b2 = Bs[tx * 4 + 2][k], b3 = Bs[tx * 4 + 3][k];
            acc[0][0] += a0v * b0; acc[0][1] += a0v * b1; acc[0][2] += a0v * b2; acc[0][3] += a0v * b3;
            acc[1][0] += a1v * b0; acc[1][1] += a1v * b1; acc[1][2] += a1v * b2; acc[1][3] += a1v * b3;
            acc[2][0] += a2v * b0; acc[2][1] += a2v * b1; acc[2][2] += a2v * b2; acc[2][3] += a2v * b3;
            acc[3][0] += a3v * b0; acc[3][1] += a3v * b1; acc[3][2] += a3v * b2; acc[3][3] += a3v * b3;
        }
        __syncthreads();
    }

    float* C = g_scratch + cOff;
#pragma unroll
    for (int i = 0; i < 4; i++) {
        int row = rowBase + ty * 4 + i;
#pragma unroll
        for (int jn = 0; jn < 4; jn++) {
            int col = colBase + tx * 4 + jn;
            float v = acc[i][jn];
            if (biasExt) v += biasExt[col];
            if (relu) v = fmaxf(v, 0.f);
            C[(size_t)row * N + col] = v;
        }
    }
}

// ---------------- persistent BiLSTM (flag barrier + pipelined h load) --------
__global__ __launch_bounds__(256, 1) void lstm_persist(
    const float* __restrict__ whhf, const float* __restrict__ whhb)
{
    int bx  = blockIdx.x;
    int dir = bx & 1;
    int s   = bx >> 1;          // 0..63
    int j0  = s * 8;
    const float* whh = dir ? whhb : whhf;

    extern __shared__ float dsh[];
    float4* h4    = (float4*)dsh;          // 2048 float4 = 32KB: h_prev[16][512]
    float*  spart = dsh + 8192;            // [8][256] = 8KB partials

    int tid = threadIdx.x;
    int row = tid & 31;
    int ks  = tid >> 5;                    // k-split 0..7 (warp-level: broadcast)
    int g   = row >> 3, jj = row & 7;
    int gr  = g * 512 + j0 + jj;

    // preload W slice into registers as f32x2 pairs
    unsigned long long wreg[32];
    {
        const ulonglong2* wsrc =
            reinterpret_cast<const ulonglong2*>(whh + (size_t)gr * 512 + ks * 64);
#pragma unroll
        for (int kk = 0; kk < 16; kk++) {
            ulonglong2 w = wsrc[kk];
            wreg[2 * kk] = w.x;
            wreg[2 * kk + 1] = w.y;
        }
    }

    // fuse-thread state (tid<64)
    int fb = tid >> 3, fj = tid & 7;
    int fcol = j0 + fj;
    float creg[2] = {0.f, 0.f};
    const float* xpb = g_scratch + XP_OFF + (size_t)dir * 4194304;
    float* hsbase = g_scratch + HS_OFF + (size_t)dir * 1048576;
    float xr[2][4];
    if (tid < 64) {
#pragma unroll
        for (int g2 = 0; g2 < 2; g2++) {
            int bb = g2 * 8 + fb;
            const float* xp = xpb + (size_t)(bb * NL) * 2048;
            xr[g2][0] = xp[fcol];
            xr[g2][1] = xp[512 + fcol];
            xr[g2][2] = xp[1024 + fcol];
            xr[g2][3] = xp[1536 + fcol];
        }
    }

    unsigned* myflag = &g_flags[dir][s][0];
    // warps 0 and 1 each poll 32 flags (one per lane), in parallel
    const unsigned* pfl = &g_flags[dir][(tid >> 5) * 32 + (tid & 31)][0];

    for (int t = 0; t < NL; t++) {
        // ---- load h_prev: first 8 batches to smem, last 8 into registers ----
        float4 hreg0, hreg1, hreg2, hreg3;
        if (t == 0) {
            float4 z = make_float4(0.f, 0.f, 0.f, 0.f);
            for (int p = tid; p < 2048; p += 256) h4[p] = z;
        } else {
            const float4* hsrc = reinterpret_cast<const float4*>(
                hsbase + (size_t)(t - 1) * 8192);
            h4[tid]       = hsrc[tid];
            h4[tid + 256] = hsrc[tid + 256];
            h4[tid + 512] = hsrc[tid + 512];
            h4[tid + 768] = hsrc[tid + 768];
            hreg0 = hsrc[1024 + tid];
            hreg1 = hsrc[1280 + tid];
            hreg2 = hsrc[1536 + tid];
            hreg3 = hsrc[1792 + tid];
        }
        __syncthreads();

        // ---- matvec + fuse in two passes of 8 batches ----
#pragma unroll 1
        for (int g2 = 0; g2 < 2; g2++) {
#pragma unroll 2
            for (int b = 0; b < 8; b++) {
                int bb = g2 * 8 + b;
                const ulonglong2* hb =
                    reinterpret_cast<const ulonglong2*>(h4 + bb * 128 + ks * 16);
                unsigned long long accA = 0ull;   // even-kk chain
                unsigned long long accB = 0ull;   // odd-kk chain
#pragma unroll
                for (int kk = 0; kk < 16; kk++) {
                    ulonglong2 h2 = hb[kk];
                    FMA_F32X2(accA, wreg[2 * kk], h2.x);
                    FMA_F32X2(accB, wreg[2 * kk + 1], h2.y);
                }
                float2 fA = *reinterpret_cast<float2*>(&accA);
                float2 fB = *reinterpret_cast<float2*>(&accB);
                spart[b * 256 + tid] = (fA.x + fA.y) + (fB.x + fB.y);
            }
            // stage second half of h after pass-0 matvec (covered by next sync)
            if (g2 == 0 && t > 0) {
                h4[1024 + tid] = hreg0;
                h4[1280 + tid] = hreg1;
                h4[1536 + tid] = hreg2;
                h4[1792 + tid] = hreg3;
            }
            __syncthreads();

            if (tid < 64) {
                int bb = g2 * 8 + fb;
                float s0 = 0.f, s1 = 0.f, s2 = 0.f, s3 = 0.f;
#pragma unroll
                for (int k2 = 0; k2 < 8; k2++) {
                    const float* pp = spart + fb * 256 + k2 * 32 + fj;
                    s0 += pp[0];
                    s1 += pp[8];
                    s2 += pp[16];
                    s3 += pp[24];
                }
                float iv = s0 + xr[g2][0];
                float fv = s1 + xr[g2][1];
                float gv = s2 + xr[g2][2];
                float ov = s3 + xr[g2][3];
                float cnew = sigm(fv) * creg[g2] + sigm(iv) * tanhf(gv);
                float hnew = sigm(ov) * tanhf(cnew);
                creg[g2] = cnew;
                hsbase[(size_t)t * 8192 + (size_t)bb * 512 + fcol] = hnew;
                if (t + 1 < NL) {   // prefetch next step's xp
                    const float* xp = xpb + (size_t)(bb * NL + t + 1) * 2048;
                    xr[g2][0] = xp[fcol];
                    xr[g2][1] = xp[512 + fcol];
                    xr[g2][2] = xp[1024 + fcol];
                    xr[g2][3] = xp[1536 + fcol];
                }
            }
            __syncthreads();
        }

        // ---- flag-broadcast barrier (2-warp parallel poll) ----
        if (tid == 0) {
            __threadfence();
            asm volatile("st.release.gpu.u32 [%0], %1;"
                         :: "l"(myflag), "r"(t + 1) : "memory");
        }
        if (tid < 64) {
            unsigned tgt = (unsigned)(t + 1);
            bool ok = false;
            do {
                unsigned r0;
                asm volatile("ld.acquire.gpu.u32 %0, [%1];"
                             : "=r"(r0) : "l"(pfl) : "memory");
                ok = (r0 >= tgt);
            } while (__ballot_sync(0xFFFFFFFFu, ok) != 0xFFFFFFFFu);
        }
        __syncthreads();
    }
}

// ---------------- oc + emi fused, float4-vectorized --------------------------
// blocks [0,1152): oc in float4 units — row has 144 float4 (128 hidden + 16 bio)
// blocks [1152,1224): emi = o @ Ew^T + eb, reading HS directly
__global__ void oc_emi_kernel(const int* __restrict__ biog,
                              const float* __restrict__ bemb,
                              const float* __restrict__ ew,
                              const float* __restrict__ eb) {
    int bx = blockIdx.x, tid = threadIdx.x;
    if (bx < 1152) {
        int idx = bx * 256 + tid;                  // < 2048*144
        int row = idx / 144, q = idx - row * 144;
        float4 v;
        if (q < 128) {
            int b = row >> 7, ll = row & 127;
            const float4* hf4 = reinterpret_cast<const float4*>(
                g_scratch + HS_OFF + (size_t)ll * 8192 + (size_t)b * 512);
            const float4* hb4 = reinterpret_cast<const float4*>(
                g_scratch + HS_OFF + 1048576 + (size_t)(NL - 1 - ll) * 8192 + (size_t)b * 512);
            float4 a = hf4[q], c = hb4[q];
            v = make_float4(0.5f * (a.x + c.x), 0.5f * (a.y + c.y),
                            0.5f * (a.z + c.z), 0.5f * (a.w + c.w));
        } else {
            const float4* be4 = reinterpret_cast<const float4*>(
                bemb + (size_t)biog[row] * NBIOE);
            v = be4[q - 128];
        }
        reinterpret_cast<float4*>(g_scratch + OC_OFF)[(size_t)row * 144 + q] = v;
    } else {
        int idx = (bx - 1152) * 256 + tid;         // < 2048*9 = 18432
        int row = idx / NT, tag = idx - row * NT;
        int b = row >> 7, ll = row & 127;
        const float4* hf4 = reinterpret_cast<const float4*>(
            g_scratch + HS_OFF + (size_t)ll * 8192 + (size_t)b * 512);
        const float4* hb4 = reinterpret_cast<const float4*>(
            g_scratch + HS_OFF + 1048576 + (size_t)(NL - 1 - ll) * 8192 + (size_t)b * 512);
        const float4* w4 = reinterpret_cast<const float4*>(ew + (size_t)tag * 512);
        float s = 0.f;
#pragma unroll 4
        for (int k = 0; k < 128; k++) {
            float4 a = hf4[k], c = hb4[k], w = w4[k];
            s += (0.5f * (a.x + c.x)) * w.x;
            s += (0.5f * (a.y + c.y)) * w.y;
            s += (0.5f * (a.z + c.z)) * w.z;
            s += (0.5f * (a.w + c.w)) * w.w;
        }
        g_scratch[EMI_OFF + idx] = s + eb[tag];
    }
}

// ---------------- fused selection + CRF (crf = block 1024) -------------------
__global__ __launch_bounds__(160) void sel_crf_kernel(
    const int* __restrict__ gold, const float* __restrict__ rel,
    const float* __restrict__ uvb,
    const int* __restrict__ tokens, const int* __restrict__ tags,
    const float* __restrict__ trans, const float* __restrict__ startv,
    const float* __restrict__ endv)
{
    int tid = threadIdx.x;

    if (blockIdx.x >= 1024) {
        __shared__ float st[81], ss[9], se[9];
        __shared__ float alpha[16][9], nxt[16][9];
        __shared__ float num[16];
        __shared__ int prev[16];
        __shared__ float res[16];
        // mask count (final_kernel divisor)
        {
            int cnt = 0;
            for (int i = tid; i < NB * NL; i += 160) cnt += (tokens[i] != 0);
#pragma unroll
            for (int off = 16; off; off >>= 1)
                cnt += __shfl_down_sync(0xFFFFFFFFu, cnt, off);
            if ((tid & 31) == 0 && cnt) atomicAdd(&g_mask_count, cnt);
        }
        if (tid < 81) st[tid] = trans[tid];
        if (tid < 9) { ss[tid] = startv[tid]; se[tid] = endv[tid]; }
        __syncthreads();
        int b = tid / 9, j = tid - b * 9;
        const float* emi = g_scratch + EMI_OFF;
        if (tid < 144) {
            alpha[b][j] = ss[j] + emi[(size_t)(b * NL) * NT + j];
            if (j == 0) {
                int t0 = tags[b * NL];
                num[b] = ss[t0] + emi[(size_t)(b * NL) * NT + t0];
                prev[b] = t0;
            }
        }
        __syncthreads();
        for (int t = 1; t < NL; t++) {
            int m = 0;
            if (tid < 144) {
                m = (tokens[b * NL + t] != 0);
                float mx = -1e30f;
#pragma unroll
                for (int i = 0; i < 9; i++) mx = fmaxf(mx, alpha[b][i] + st[i * 9 + j]);
                float sv = 0.f;
#pragma unroll
                for (int i = 0; i < 9; i++) sv += expf(alpha[b][i] + st[i * 9 + j] - mx);
                float nv = mx + logf(sv) + emi[(size_t)(b * NL + t) * NT + j];
                nxt[b][j] = m ? nv : alpha[b][j];
            }
            __syncthreads();
            if (tid < 144) {
                alpha[b][j] = nxt[b][j];
                if (j == 0 && m) {
                    int tg = tags[b * NL + t];
                    num[b] += st[prev[b] * 9 + tg] + emi[(size_t)(b * NL + t) * NT + tg];
                    prev[b] = tg;
                }
            }
            __syncthreads();
        }
        if (tid < 16) {
            float nb = num[tid] + se[prev[tid]];
            float mx = -1e30f;
            for (int i2 = 0; i2 < 9; i2++) mx = fmaxf(mx, alpha[tid][i2] + se[i2]);
            float sv = 0.f;
            for (int i2 = 0; i2 < 9; i2++) sv += expf(alpha[tid][i2] + se[i2] - mx);
            res[tid] = nb - (mx + logf(sv));
        }
        __syncthreads();
        if (tid == 0) {
            float tot = 0.f;
            for (int i2 = 0; i2 < 16; i2++) tot += res[i2];
            g_crf_loss = -tot / 16.f;
        }
        return;
    }

    // ---------------- selection path ----------------
    __shared__ __align__(16) float srel[NR * NREL];   // 25.6KB
    __shared__ __align__(16) float sv0[NREL], sv1[NREL];
    __shared__ float sred[4];

    int bx = blockIdx.x;
    int b  = bx >> 6;
    int i0 = (bx & 63) << 1;

    // block-level mask exit: both i rows masked -> contribution is exactly 0
    float mi0 = g_scratch[MASKF_OFF + b * NL + i0];
    float mi1 = g_scratch[MASKF_OFF + b * NL + i0 + 1];
    if (mi0 == 0.f && mi1 == 0.f) return;

    for (int p = tid; p < NR * NREL; p += 160) srel[p] = rel[p];
    if (tid < 128) {
        const float* v2 = g_scratch + V2_OFF;
        sv0[tid] = v2[(size_t)(b * NL + i0) * NREL + tid] + uvb[tid];
        sv1[tid] = v2[(size_t)(b * NL + i0 + 1) * NREL + tid] + uvb[tid];
    }
    __syncthreads();

    if (tid < 128) {
        int j = tid;
        float mj = g_scratch[MASKF_OFF + b * NL + j];
        // warp-level skip: if every j in this warp is masked, contribution is 0
        if (__ballot_sync(0xFFFFFFFFu, mj != 0.f) == 0u) {
            if ((tid & 31) == 0) sred[tid >> 5] = 0.f;
        } else {
            const float4* u1r = reinterpret_cast<const float4*>(g_scratch + U1_OFF + (size_t)(b * NL + j) * NREL);
            const float4* s0_4 = reinterpret_cast<const float4*>(sv0);
            const float4* s1_4 = reinterpret_cast<const float4*>(sv1);
            const float4* rel4 = reinterpret_cast<const float4*>(srel);

            float acc0[NR], acc1[NR];
#pragma unroll
            for (int r = 0; r < NR; r++) { acc0[r] = 0.f; acc1[r] = 0.f; }

#pragma unroll 4
            for (int h4 = 0; h4 < 32; h4++) {
                float4 uu = u1r[h4];
                float4 a = s0_4[h4];
                float4 c = s1_4[h4];
                float x0x = fmaxf(uu.x + a.x, 0.f), x0y = fmaxf(uu.y + a.y, 0.f);
                float x0z = fmaxf(uu.z + a.z, 0.f), x0w = fmaxf(uu.w + a.w, 0.f);
                float x1x = fmaxf(uu.x + c.x, 0.f), x1y = fmaxf(uu.y + c.y, 0.f);
                float x1z = fmaxf(uu.z + c.z, 0.f), x1w = fmaxf(uu.w + c.w, 0.f);
#pragma unroll
                for (int r = 0; r < NR; r++) {
                    float4 rv = rel4[r * 32 + h4];
                    acc0[r] += x0x * rv.x + x0y * rv.y + x0z * rv.z + x0w * rv.w;
                    acc1[r] += x1x * rv.x + x1y * rv.y + x1z * rv.z + x1w * rv.w;
                }
            }

            const int* g0 = gold + (size_t)(b * NL + i0) * NR * NL + j;
            const int* g1 = gold + (size_t)(b * NL + i0 + 1) * NR * NL + j;
            float s0 = 0.f, s1 = 0.f;
#pragma unroll
            for (int r = 0; r < NR; r++) {
                float x = acc0[r];
                float gg = (float)g0[(size_t)r * NL];
                s0 += fmaxf(x, 0.f) - x * gg + log1pf(expf(-fabsf(x)));
                x = acc1[r];
                gg = (float)g1[(size_t)r * NL];
                s1 += fmaxf(x, 0.f) - x * gg + log1pf(expf(-fabsf(x)));
            }
            float part = mj * (mi0 * s0 + mi1 * s1);

#pragma unroll
            for (int off = 16; off; off >>= 1) part += __shfl_down_sync(0xFFFFFFFFu, part, off);
            if ((tid & 31) == 0) sred[tid >> 5] = part;
        }
    }
    __syncthreads();
    if (tid == 0) {
        double tot = (double)sred[0] + (double)sred[1] + (double)sred[2] + (double)sred[3];
        atomicAdd(&g_sel_sum, tot);
    }
}

// ---------------- final scalar ----------------
__global__ void final_kernel(float* out) {
    out[0] = g_crf_loss + (float)(g_sel_sum / (double)g_mask_count);
}

// ============================================================================
extern "C" void kernel_launch(void* const* d_in, const int* in_sizes, int n_in,
                              void* d_out, int out_size)
{
    const int*   tokens     = (const int*)d_in[0];
    const int*   bio_gold   = (const int*)d_in[1];
    const int*   sel_gold   = (const int*)d_in[2];
    // d_in[3] = is_train (unused)
    const float* word_emb   = (const float*)d_in[4];
    const float* rel_emb    = (const float*)d_in[5];
    const float* bio_emb    = (const float*)d_in[6];
    const float* w_ih_f     = (const float*)d_in[7];
    const float* w_hh_f     = (const float*)d_in[8];
    const float* b_ih_f     = (const float*)d_in[9];
    const float* b_hh_f     = (const float*)d_in[10];
    const float* w_ih_b     = (const float*)d_in[11];
    const float* w_hh_b     = (const float*)d_in[12];
    const float* b_ih_b     = (const float*)d_in[13];
    const float* b_hh_b     = (const float*)d_in[14];
    const float* emission_w = (const float*)d_in[15];
    const float* emission_b = (const float*)d_in[16];
    const float* sel_u_w    = (const float*)d_in[17];
    const float* sel_u_b    = (const float*)d_in[18];
    const float* sel_v_w    = (const float*)d_in[19];
    const float* sel_v_b    = (const float*)d_in[20];
    const float* sel_uv_w   = (const float*)d_in[21];
    const float* sel_uv_b   = (const float*)d_in[22];
    const float* crf_trans  = (const float*)d_in[23];
    const float* crf_start  = (const float*)d_in[24];
    const float* crf_end    = (const float*)d_in[25];

    // embed + bsum + accumulator zeroing in one launch
    prep_kernel<<<2417, 256>>>(tokens, word_emb,
                               b_ih_f, b_hh_f, b_ih_b, b_hh_b);

    // fused input projection for both directions
    xproj_gemm<<<dim3(64, 16), 256>>>(w_ih_f, w_ih_b);

    // persistent BiLSTM (40KB dynamic smem, flag-broadcast barrier)
    lstm_persist<<<128, 256, 40960>>>(w_hh_f, w_hh_b);

    // oc concat (float4) + emission in one launch
    oc_emi_kernel<<<1224, 256>>>(bio_gold, bio_emb, emission_w, emission_b);

    // u = relu(oc@u_w^T+b) and v = relu(oc@v_w^T+b) in one launch
    sgemm_nt2<<<dim3(2, 32, 2), 256>>>(OC_OFF, OC_OFF, 576,
                                       sel_u_w, sel_v_w, 576,
                                       U_OFF, V_OFF, NREL, 576,
                                       sel_u_b, sel_v_b, 1);
    // u1 = u@w1^T and v2 = v@w2^T in one launch
    sgemm_nt2<<<dim3(2, 32, 2), 256>>>(U_OFF, V_OFF, NREL,
                                       sel_uv_w, sel_uv_w + NREL, 2 * NREL,
                                       U1_OFF, V2_OFF, NREL, NREL,
                                       nullptr, nullptr, 0);

    // selection loss (1024 blocks) + CRF/mask-count (block 1024) overlapped
    sel_crf_kernel<<<1025, 160>>>(sel_gold, rel_emb, sel_uv_b,
                                  tokens, bio_gold,
                                  crf_trans, crf_start, crf_end);
    final_kernel<<<1, 1>>>((float*)d_out);
}

// round 17
// speedup vs baseline: 1.0443x; 1.0443x over previous
#include <cuda_runtime.h>
#include <cstdint>

// Problem constants
#define NB   16
#define NL   128
#define NE   300
#define NH   512
#define NT   9
#define NBIOE 64
#define NREL 128
#define NR   50

// ---------------- scratch layout (floats) ----------------
#define EMB_OFF    0            // 2048*300
#define BSUM_OFF   1228800      // 2*2048
#define XP_OFF     1232896      // 2 * 2048*2048
#define HS_OFF     9621504      // 2 * 128*16*512
#define EMI_OFF    12783616     // 2048*9
#define OC_OFF     12802048     // 2048*576
#define U_OFF      13981696     // 2048*128
#define V_OFF      14243840     // 2048*128
#define U1_OFF     14505984     // 2048*128
#define V2_OFF     14768128     // 2048*128
#define MASKF_OFF  15030272     // 2048
#define SCRATCH_SZ 15032320

__device__ __align__(16) float g_scratch[SCRATCH_SZ];
__device__ double g_sel_sum;
__device__ int    g_mask_count;
__device__ float  g_crf_loss;
// per-block step flags: [dir][slice], each on its own 128B line
__device__ unsigned g_flags[2][64][32];

__device__ __forceinline__ float sigm(float x) { return 1.f / (1.f + expf(-x)); }

#define FMA_F32X2(d, a, b) \
    asm("fma.rn.f32x2 %0, %1, %2, %0;" : "+l"(d) : "l"(a), "l"(b))

// ---------------- prep: embed gather + mask, bias sums, accumulator zeroing --
__global__ void prep_kernel(const int* __restrict__ tokens,
                            const float* __restrict__ wemb,
                            const float* bif, const float* bhf,
                            const float* bib, const float* bhb) {
    int bx = blockIdx.x, tid = threadIdx.x;
    if (bx < 2400) {
        int idx = bx * 256 + tid;                  // < 2048*300
        int bl = idx / NE;
        int e  = idx - bl * NE;
        int tok = tokens[bl];
        g_scratch[EMB_OFF + idx] = wemb[(size_t)tok * NE + e];
        if (e == 0) g_scratch[MASKF_OFF + bl] = (tok != 0) ? 1.f : 0.f;
    } else if (bx < 2416) {
        int idx = (bx - 2400) * 256 + tid;         // < 4096
        int d = idx >> 11, g = idx & 2047;
        g_scratch[BSUM_OFF + idx] = d ? (bib[g] + bhb[g]) : (bif[g] + bhf[g]);
    } else {
        if (tid == 0) {
            g_sel_sum = 0.0;
            g_mask_count = 0;
            g_crf_loss = 0.f;
        }
        if (tid < 128) g_flags[tid >> 6][tid & 63][0] = 0u;
    }
}

// ---------------- fused xproj GEMM (proven: 125us) ---------------------------
#define KTILE 16
__global__ __launch_bounds__(256) void xproj_gemm(
    const float* __restrict__ wf, const float* __restrict__ wb)
{
    __shared__ float As[KTILE][132];
    __shared__ float Bs[KTILE][68];
    int tid = threadIdx.x;
    int tx = tid & 15, ty = tid >> 4;
    int rowBase = blockIdx.y * 128;
    int colBase = blockIdx.x * 64;
    int dir = colBase >> 11;
    const float* Bmat = dir ? wb : wf;
    int gcol0 = colBase & 2047;

    float acc[8][4];
#pragma unroll
    for (int i = 0; i < 8; i++)
#pragma unroll
        for (int j = 0; j < 4; j++) acc[i][j] = 0.f;

    for (int k0 = 0; k0 < NE; k0 += KTILE) {
#pragma unroll
        for (int i = 0; i < 2; i++) {
            int f = tid + i * 256;
            int r = f >> 2, kq = f & 3;
            int gk = k0 + kq * 4;
            float4 v = make_float4(0.f, 0.f, 0.f, 0.f);
            if (gk < NE)
                v = *reinterpret_cast<const float4*>(
                        &g_scratch[EMB_OFF + (size_t)(rowBase + r) * NE + gk]);
            As[kq * 4 + 0][r] = v.x;
            As[kq * 4 + 1][r] = v.y;
            As[kq * 4 + 2][r] = v.z;
            As[kq * 4 + 3][r] = v.w;
        }
        {
            int n = tid >> 2, kq = tid & 3;
            int gk = k0 + kq * 4;
            float4 v = make_float4(0.f, 0.f, 0.f, 0.f);
            if (gk < NE)
                v = *reinterpret_cast<const float4*>(
                        &Bmat[(size_t)(gcol0 + n) * NE + gk]);
            Bs[kq * 4 + 0][n] = v.x;
            Bs[kq * 4 + 1][n] = v.y;
            Bs[kq * 4 + 2][n] = v.z;
            Bs[kq * 4 + 3][n] = v.w;
        }
        __syncthreads();
#pragma unroll
        for (int k = 0; k < KTILE; k++) {
            float4 a0 = *reinterpret_cast<const float4*>(&As[k][ty * 8]);
            float4 a1 = *reinterpret_cast<const float4*>(&As[k][ty * 8 + 4]);
            float4 bq = *reinterpret_cast<const float4*>(&Bs[k][tx * 4]);
            acc[0][0] += a0.x * bq.x; acc[0][1] += a0.x * bq.y; acc[0][2] += a0.x * bq.z; acc[0][3] += a0.x * bq.w;
            acc[1][0] += a0.y * bq.x; acc[1][1] += a0.y * bq.y; acc[1][2] += a0.y * bq.z; acc[1][3] += a0.y * bq.w;
            acc[2][0] += a0.z * bq.x; acc[2][1] += a0.z * bq.y; acc[2][2] += a0.z * bq.z; acc[2][3] += a0.z * bq.w;
            acc[3][0] += a0.w * bq.x; acc[3][1] += a0.w * bq.y; acc[3][2] += a0.w * bq.z; acc[3][3] += a0.w * bq.w;
            acc[4][0] += a1.x * bq.x; acc[4][1] += a1.x * bq.y; acc[4][2] += a1.x * bq.z; acc[4][3] += a1.x * bq.w;
            acc[5][0] += a1.y * bq.x; acc[5][1] += a1.y * bq.y; acc[5][2] += a1.y * bq.z; acc[5][3] += a1.y * bq.w;
            acc[6][0] += a1.z * bq.x; acc[6][1] += a1.z * bq.y; acc[6][2] += a1.z * bq.z; acc[6][3] += a1.z * bq.w;
            acc[7][0] += a1.w * bq.x; acc[7][1] += a1.w * bq.y; acc[7][2] += a1.w * bq.z; acc[7][3] += a1.w * bq.w;
        }
        __syncthreads();
    }

    float4 bias = *reinterpret_cast<const float4*>(
        &g_scratch[BSUM_OFF + dir * 2048 + gcol0 + tx * 4]);
    int b = rowBase >> 7;
#pragma unroll
    for (int i = 0; i < 8; i++) {
        int rw = ty * 8 + i;
        int lo = dir ? (127 - rw) : rw;
        float4 v = make_float4(acc[i][0] + bias.x, acc[i][1] + bias.y,
                               acc[i][2] + bias.z, acc[i][3] + bias.w);
        *reinterpret_cast<float4*>(
            &g_scratch[XP_OFF + (size_t)dir * 4194304
                       + (size_t)(b * 128 + lo) * 2048 + gcol0 + tx * 4]) = v;
    }
}

// ---------------- dual NT SGEMM: blockIdx.z picks (A,B,C,bias) set -----------
__global__ __launch_bounds__(256) void sgemm_nt2(
    int a0, int a1, int lda,
    const float* __restrict__ B0, const float* __restrict__ B1, int ldb,
    int c0, int c1, int N, int K,
    const float* __restrict__ bias0, const float* __restrict__ bias1, int relu)
{
    __shared__ float As[64][33];
    __shared__ float Bs[64][33];
    int z = blockIdx.z;
    int aOff = z ? a1 : a0;
    int cOff = z ? c1 : c0;
    const float* Bm = z ? B1 : B0;
    const float* biasExt = z ? bias1 : bias0;

    int tid = threadIdx.x;
    int tx = tid & 15, ty = tid >> 4;
    int rowBase = blockIdx.y * 64;
    int colBase = blockIdx.x * 64;
    const float* A = g_scratch + aOff;

    float acc[4][4];
#pragma unroll
    for (int i = 0; i < 4; i++)
#pragma unroll
        for (int j = 0; j < 4; j++) acc[i][j] = 0.f;

    for (int k0 = 0; k0 < K; k0 += 32) {
#pragma unroll
        for (int i = 0; i < 8; i++) {
            int p = tid + i * 256;
            int r = p >> 5, c = p & 31;
            int gk = k0 + c;
            As[r][c] = (gk < K) ? A[(size_t)(rowBase + r) * lda + gk] : 0.f;
            Bs[r][c] = (gk < K) ? Bm[(size_t)(colBase + r) * ldb + gk] : 0.f;
        }
        __syncthreads();
#pragma unroll
        for (int k = 0; k < 32; k++) {
            float a0v = As[ty * 4 + 0][k], a1v = As[ty * 4 + 1][k];
            float a2v = As[ty * 4 + 2][k], a3v = As[ty * 4 + 3][k];
            float b0 = Bs[tx * 4 + 0][k], b1 = Bs[tx * 4 + 1][k];
            float b2 = Bs[tx * 4 + 2][k], b3 = Bs[tx * 4 + 3][k];
            acc[0][0] += a0v * b0; acc[0][1] += a0v * b1; acc[0][2] += a0v * b2; acc[0][3] += a0v * b3;
            acc[1][0] += a1v * b0; acc[1][1] += a1v * b1; acc[1][2] += a1v * b2; acc[1][3] += a1v * b3;
            acc[2][0] += a2v * b0; acc[2][1] += a2v * b1; acc[2][2] += a2v * b2; acc[2][3] += a2v * b3;
            acc[3][0] += a3v * b0; acc[3][1] += a3v * b1; acc[3][2] += a3v * b2; acc[3][3] += a3v * b3;
        }
        __syncthreads();
    }

    float* C = g_scratch + cOff;
#pragma unroll
    for (int i = 0; i < 4; i++) {
        int row = rowBase + ty * 4 + i;
#pragma unroll
        for (int jn = 0; jn < 4; jn++) {
            int col = colBase + tx * 4 + jn;
            float v = acc[i][jn];
            if (biasExt) v += biasExt[col];
            if (relu) v = fmaxf(v, 0.f);
            C[(size_t)row * N + col] = v;
        }
    }
}

// ---------------- persistent BiLSTM (flag barrier + pipelined h load) --------
__global__ __launch_bounds__(256, 1) void lstm_persist(
    const float* __restrict__ whhf, const float* __restrict__ whhb)
{
    int bx  = blockIdx.x;
    int dir = bx & 1;
    int s   = bx >> 1;          // 0..63
    int j0  = s * 8;
    const float* whh = dir ? whhb : whhf;

    extern __shared__ float dsh[];
    float4* h4    = (float4*)dsh;          // 2048 float4 = 32KB: h_prev[16][512]
    float*  spart = dsh + 8192;            // [8][256] = 8KB partials

    int tid = threadIdx.x;
    int row = tid & 31;
    int ks  = tid >> 5;                    // k-split 0..7 (warp-level: broadcast)
    int g   = row >> 3, jj = row & 7;
    int gr  = g * 512 + j0 + jj;

    // preload W slice into registers as f32x2 pairs
    unsigned long long wreg[32];
    {
        const ulonglong2* wsrc =
            reinterpret_cast<const ulonglong2*>(whh + (size_t)gr * 512 + ks * 64);
#pragma unroll
        for (int kk = 0; kk < 16; kk++) {
            ulonglong2 w = wsrc[kk];
            wreg[2 * kk] = w.x;
            wreg[2 * kk + 1] = w.y;
        }
    }

    // fuse-thread state (tid<64)
    int fb = tid >> 3, fj = tid & 7;
    int fcol = j0 + fj;
    float creg[2] = {0.f, 0.f};
    const float* xpb = g_scratch + XP_OFF + (size_t)dir * 4194304;
    float* hsbase = g_scratch + HS_OFF + (size_t)dir * 1048576;
    float xr[2][4];
    if (tid < 64) {
#pragma unroll
        for (int g2 = 0; g2 < 2; g2++) {
            int bb = g2 * 8 + fb;
            const float* xp = xpb + (size_t)(bb * NL) * 2048;
            xr[g2][0] = xp[fcol];
            xr[g2][1] = xp[512 + fcol];
            xr[g2][2] = xp[1024 + fcol];
            xr[g2][3] = xp[1536 + fcol];
        }
    }

    unsigned* myflag = &g_flags[dir][s][0];
    // warps 0 and 1 each poll 32 flags (one per lane), in parallel
    const unsigned* pfl = &g_flags[dir][(tid >> 5) * 32 + (tid & 31)][0];

    for (int t = 0; t < NL; t++) {
        // ---- load h_prev: first 8 batches to smem, last 8 into registers ----
        float4 hreg0, hreg1, hreg2, hreg3;
        if (t == 0) {
            float4 z = make_float4(0.f, 0.f, 0.f, 0.f);
            for (int p = tid; p < 2048; p += 256) h4[p] = z;
        } else {
            const float4* hsrc = reinterpret_cast<const float4*>(
                hsbase + (size_t)(t - 1) * 8192);
            h4[tid]       = hsrc[tid];
            h4[tid + 256] = hsrc[tid + 256];
            h4[tid + 512] = hsrc[tid + 512];
            h4[tid + 768] = hsrc[tid + 768];
            hreg0 = hsrc[1024 + tid];
            hreg1 = hsrc[1280 + tid];
            hreg2 = hsrc[1536 + tid];
            hreg3 = hsrc[1792 + tid];
        }
        __syncthreads();

        // ---- matvec + fuse in two passes of 8 batches ----
#pragma unroll 1
        for (int g2 = 0; g2 < 2; g2++) {
#pragma unroll 2
            for (int b = 0; b < 8; b++) {
                int bb = g2 * 8 + b;
                const ulonglong2* hb =
                    reinterpret_cast<const ulonglong2*>(h4 + bb * 128 + ks * 16);
                unsigned long long accA = 0ull;   // even-kk chain
                unsigned long long accB = 0ull;   // odd-kk chain
#pragma unroll
                for (int kk = 0; kk < 16; kk++) {
                    ulonglong2 h2 = hb[kk];
                    FMA_F32X2(accA, wreg[2 * kk], h2.x);
                    FMA_F32X2(accB, wreg[2 * kk + 1], h2.y);
                }
                float2 fA = *reinterpret_cast<float2*>(&accA);
                float2 fB = *reinterpret_cast<float2*>(&accB);
                spart[b * 256 + tid] = (fA.x + fA.y) + (fB.x + fB.y);
            }
            // stage second half of h after pass-0 matvec (covered by next sync)
            if (g2 == 0 && t > 0) {
                h4[1024 + tid] = hreg0;
                h4[1280 + tid] = hreg1;
                h4[1536 + tid] = hreg2;
                h4[1792 + tid] = hreg3;
            }
            __syncthreads();

            if (tid < 64) {
                int bb = g2 * 8 + fb;
                float s0 = 0.f, s1 = 0.f, s2 = 0.f, s3 = 0.f;
#pragma unroll
                for (int k2 = 0; k2 < 8; k2++) {
                    const float* pp = spart + fb * 256 + k2 * 32 + fj;
                    s0 += pp[0];
                    s1 += pp[8];
                    s2 += pp[16];
                    s3 += pp[24];
                }
                float iv = s0 + xr[g2][0];
                float fv = s1 + xr[g2][1];
                float gv = s2 + xr[g2][2];
                float ov = s3 + xr[g2][3];
                float cnew = sigm(fv) * creg[g2] + sigm(iv) * tanhf(gv);
                float hnew = sigm(ov) * tanhf(cnew);
                creg[g2] = cnew;
                hsbase[(size_t)t * 8192 + (size_t)bb * 512 + fcol] = hnew;
                if (t + 1 < NL) {   // prefetch next step's xp
                    const float* xp = xpb + (size_t)(bb * NL + t + 1) * 2048;
                    xr[g2][0] = xp[fcol];
                    xr[g2][1] = xp[512 + fcol];
                    xr[g2][2] = xp[1024 + fcol];
                    xr[g2][3] = xp[1536 + fcol];
                }
            }
            __syncthreads();
        }

        // ---- flag-broadcast barrier (2-warp parallel poll) ----
        if (tid == 0) {
            __threadfence();
            asm volatile("st.release.gpu.u32 [%0], %1;"
                         :: "l"(myflag), "r"(t + 1) : "memory");
        }
        if (tid < 64) {
            unsigned tgt = (unsigned)(t + 1);
            bool ok = false;
            do {
                unsigned r0;
                asm volatile("ld.acquire.gpu.u32 %0, [%1];"
                             : "=r"(r0) : "l"(pfl) : "memory");
                ok = (r0 >= tgt);
            } while (__ballot_sync(0xFFFFFFFFu, ok) != 0xFFFFFFFFu);
        }
        __syncthreads();
    }
}

// ---------------- oc + emi fused --------------------------------------------
// blocks [0,1152): oc in float4 units — row has 144 float4 (128 hidden + 16 bio)
// blocks [1152,1408): emi, WARP-PER-ROW: lanes split the 512-wide reduction
// (16 elems each), 9 tags per warp, shfl-tree reduce.
__global__ void oc_emi_kernel(const int* __restrict__ biog,
                              const float* __restrict__ bemb,
                              const float* __restrict__ ew,
                              const float* __restrict__ eb) {
    int bx = blockIdx.x, tid = threadIdx.x;
    if (bx < 1152) {
        int idx = bx * 256 + tid;                  // < 2048*144
        int row = idx / 144, q = idx - row * 144;
        float4 v;
        if (q < 128) {
            int b = row >> 7, ll = row & 127;
            const float4* hf4 = reinterpret_cast<const float4*>(
                g_scratch + HS_OFF + (size_t)ll * 8192 + (size_t)b * 512);
            const float4* hb4 = reinterpret_cast<const float4*>(
                g_scratch + HS_OFF + 1048576 + (size_t)(NL - 1 - ll) * 8192 + (size_t)b * 512);
            float4 a = hf4[q], c = hb4[q];
            v = make_float4(0.5f * (a.x + c.x), 0.5f * (a.y + c.y),
                            0.5f * (a.z + c.z), 0.5f * (a.w + c.w));
        } else {
            const float4* be4 = reinterpret_cast<const float4*>(
                bemb + (size_t)biog[row] * NBIOE);
            v = be4[q - 128];
        }
        reinterpret_cast<float4*>(g_scratch + OC_OFF)[(size_t)row * 144 + q] = v;
    } else {
        // stage emission weights in shared: ew[9][512] + eb[9]
        __shared__ __align__(16) float sew[NT * NH];
        __shared__ float seb[NT];
        for (int p = tid; p < NT * NH; p += 256) sew[p] = ew[p];
        if (tid < NT) seb[tid] = eb[tid];
        __syncthreads();

        int wid = tid >> 5, lane = tid & 31;
        int row = (bx - 1152) * 8 + wid;           // < 2048
        int b = row >> 7, ll = row & 127;
        const float4* hf4 = reinterpret_cast<const float4*>(
            g_scratch + HS_OFF + (size_t)ll * 8192 + (size_t)b * 512) + lane * 4;
        const float4* hb4 = reinterpret_cast<const float4*>(
            g_scratch + HS_OFF + 1048576 + (size_t)(NL - 1 - ll) * 8192 + (size_t)b * 512) + lane * 4;
        // this lane's 16 o-values
        float ov[16];
#pragma unroll
        for (int q = 0; q < 4; q++) {
            float4 a = hf4[q], c = hb4[q];
            ov[4 * q + 0] = 0.5f * (a.x + c.x);
            ov[4 * q + 1] = 0.5f * (a.y + c.y);
            ov[4 * q + 2] = 0.5f * (a.z + c.z);
            ov[4 * q + 3] = 0.5f * (a.w + c.w);
        }
#pragma unroll
        for (int tag = 0; tag < NT; tag++) {
            const float4* w4 = reinterpret_cast<const float4*>(sew + tag * NH) + lane * 4;
            float s = 0.f;
#pragma unroll
            for (int q = 0; q < 4; q++) {
                float4 w = w4[q];
                s += ov[4 * q + 0] * w.x + ov[4 * q + 1] * w.y
                   + ov[4 * q + 2] * w.z + ov[4 * q + 3] * w.w;
            }
#pragma unroll
            for (int off = 16; off; off >>= 1)
                s += __shfl_down_sync(0xFFFFFFFFu, s, off);
            if (lane == 0)
                g_scratch[EMI_OFF + (size_t)row * NT + tag] = s + seb[tag];
        }
    }
}

// ---------------- fused selection + CRF (crf = block 1024) -------------------
__global__ __launch_bounds__(160) void sel_crf_kernel(
    const int* __restrict__ gold, const float* __restrict__ rel,
    const float* __restrict__ uvb,
    const int* __restrict__ tokens, const int* __restrict__ tags,
    const float* __restrict__ trans, const float* __restrict__ startv,
    const float* __restrict__ endv)
{
    int tid = threadIdx.x;

    if (blockIdx.x >= 1024) {
        __shared__ float st[81], ss[9], se[9];
        __shared__ float alpha[16][9], nxt[16][9];
        __shared__ float num[16];
        __shared__ int prev[16];
        __shared__ float res[16];
        // mask count (final_kernel divisor)
        {
            int cnt = 0;
            for (int i = tid; i < NB * NL; i += 160) cnt += (tokens[i] != 0);
#pragma unroll
            for (int off = 16; off; off >>= 1)
                cnt += __shfl_down_sync(0xFFFFFFFFu, cnt, off);
            if ((tid & 31) == 0 && cnt) atomicAdd(&g_mask_count, cnt);
        }
        if (tid < 81) st[tid] = trans[tid];
        if (tid < 9) { ss[tid] = startv[tid]; se[tid] = endv[tid]; }
        __syncthreads();
        int b = tid / 9, j = tid - b * 9;
        const float* emi = g_scratch + EMI_OFF;
        if (tid < 144) {
            alpha[b][j] = ss[j] + emi[(size_t)(b * NL) * NT + j];
            if (j == 0) {
                int t0 = tags[b * NL];
                num[b] = ss[t0] + emi[(size_t)(b * NL) * NT + t0];
                prev[b] = t0;
            }
        }
        __syncthreads();
        for (int t = 1; t < NL; t++) {
            int m = 0;
            if (tid < 144) {
                m = (tokens[b * NL + t] != 0);
                float mx = -1e30f;
#pragma unroll
                for (int i = 0; i < 9; i++) mx = fmaxf(mx, alpha[b][i] + st[i * 9 + j]);
                float sv = 0.f;
#pragma unroll
                for (int i = 0; i < 9; i++) sv += expf(alpha[b][i] + st[i * 9 + j] - mx);
                float nv = mx + logf(sv) + emi[(size_t)(b * NL + t) * NT + j];
                nxt[b][j] = m ? nv : alpha[b][j];
            }
            __syncthreads();
            if (tid < 144) {
                alpha[b][j] = nxt[b][j];
                if (j == 0 && m) {
                    int tg = tags[b * NL + t];
                    num[b] += st[prev[b] * 9 + tg] + emi[(size_t)(b * NL + t) * NT + tg];
                    prev[b] = tg;
                }
            }
            __syncthreads();
        }
        if (tid < 16) {
            float nb = num[tid] + se[prev[tid]];
            float mx = -1e30f;
            for (int i2 = 0; i2 < 9; i2++) mx = fmaxf(mx, alpha[tid][i2] + se[i2]);
            float sv = 0.f;
            for (int i2 = 0; i2 < 9; i2++) sv += expf(alpha[tid][i2] + se[i2] - mx);
            res[tid] = nb - (mx + logf(sv));
        }
        __syncthreads();
        if (tid == 0) {
            float tot = 0.f;
            for (int i2 = 0; i2 < 16; i2++) tot += res[i2];
            g_crf_loss = -tot / 16.f;
        }
        return;
    }

    // ---------------- selection path ----------------
    __shared__ __align__(16) float srel[NR * NREL];   // 25.6KB
    __shared__ __align__(16) float sv0[NREL], sv1[NREL];
    __shared__ float sred[4];

    int bx = blockIdx.x;
    int b  = bx >> 6;
    int i0 = (bx & 63) << 1;

    // block-level mask exit: both i rows masked -> contribution is exactly 0
    float mi0 = g_scratch[MASKF_OFF + b * NL + i0];
    float mi1 = g_scratch[MASKF_OFF + b * NL + i0 + 1];
    if (mi0 == 0.f && mi1 == 0.f) return;

    for (int p = tid; p < NR * NREL; p += 160) srel[p] = rel[p];
    if (tid < 128) {
        const float* v2 = g_scratch + V2_OFF;
        sv0[tid] = v2[(size_t)(b * NL + i0) * NREL + tid] + uvb[tid];
        sv1[tid] = v2[(size_t)(b * NL + i0 + 1) * NREL + tid] + uvb[tid];
    }
    __syncthreads();

    if (tid < 128) {
        int j = tid;
        float mj = g_scratch[MASKF_OFF + b * NL + j];
        // warp-level skip: if every j in this warp is masked, contribution is 0
        if (__ballot_sync(0xFFFFFFFFu, mj != 0.f) == 0u) {
            if ((tid & 31) == 0) sred[tid >> 5] = 0.f;
        } else {
            const float4* u1r = reinterpret_cast<const float4*>(g_scratch + U1_OFF + (size_t)(b * NL + j) * NREL);
            const float4* s0_4 = reinterpret_cast<const float4*>(sv0);
            const float4* s1_4 = reinterpret_cast<const float4*>(sv1);
            const float4* rel4 = reinterpret_cast<const float4*>(srel);

            float acc0[NR], acc1[NR];
#pragma unroll
            for (int r = 0; r < NR; r++) { acc0[r] = 0.f; acc1[r] = 0.f; }

#pragma unroll 4
            for (int h4 = 0; h4 < 32; h4++) {
                float4 uu = u1r[h4];
                float4 a = s0_4[h4];
                float4 c = s1_4[h4];
                float x0x = fmaxf(uu.x + a.x, 0.f), x0y = fmaxf(uu.y + a.y, 0.f);
                float x0z = fmaxf(uu.z + a.z, 0.f), x0w = fmaxf(uu.w + a.w, 0.f);
                float x1x = fmaxf(uu.x + c.x, 0.f), x1y = fmaxf(uu.y + c.y, 0.f);
                float x1z = fmaxf(uu.z + c.z, 0.f), x1w = fmaxf(uu.w + c.w, 0.f);
#pragma unroll
                for (int r = 0; r < NR; r++) {
                    float4 rv = rel4[r * 32 + h4];
                    acc0[r] += x0x * rv.x + x0y * rv.y + x0z * rv.z + x0w * rv.w;
                    acc1[r] += x1x * rv.x + x1y * rv.y + x1z * rv.z + x1w * rv.w;
                }
            }

            const int* g0 = gold + (size_t)(b * NL + i0) * NR * NL + j;
            const int* g1 = gold + (size_t)(b * NL + i0 + 1) * NR * NL + j;
            float s0 = 0.f, s1 = 0.f;
#pragma unroll
            for (int r = 0; r < NR; r++) {
                float x = acc0[r];
                float gg = (float)g0[(size_t)r * NL];
                s0 += fmaxf(x, 0.f) - x * gg + log1pf(expf(-fabsf(x)));
                x = acc1[r];
                gg = (float)g1[(size_t)r * NL];
                s1 += fmaxf(x, 0.f) - x * gg + log1pf(expf(-fabsf(x)));
            }
            float part = mj * (mi0 * s0 + mi1 * s1);

#pragma unroll
            for (int off = 16; off; off >>= 1) part += __shfl_down_sync(0xFFFFFFFFu, part, off);
            if ((tid & 31) == 0) sred[tid >> 5] = part;
        }
    }
    __syncthreads();
    if (tid == 0) {
        double tot = (double)sred[0] + (double)sred[1] + (double)sred[2] + (double)sred[3];
        atomicAdd(&g_sel_sum, tot);
    }
}

// ---------------- final scalar ----------------
__global__ void final_kernel(float* out) {
    out[0] = g_crf_loss + (float)(g_sel_sum / (double)g_mask_count);
}

// ============================================================================
extern "C" void kernel_launch(void* const* d_in, const int* in_sizes, int n_in,
                              void* d_out, int out_size)
{
    const int*   tokens     = (const int*)d_in[0];
    const int*   bio_gold   = (const int*)d_in[1];
    const int*   sel_gold   = (const int*)d_in[2];
    // d_in[3] = is_train (unused)
    const float* word_emb   = (const float*)d_in[4];
    const float* rel_emb    = (const float*)d_in[5];
    const float* bio_emb    = (const float*)d_in[6];
    const float* w_ih_f     = (const float*)d_in[7];
    const float* w_hh_f     = (const float*)d_in[8];
    const float* b_ih_f     = (const float*)d_in[9];
    const float* b_hh_f     = (const float*)d_in[10];
    const float* w_ih_b     = (const float*)d_in[11];
    const float* w_hh_b     = (const float*)d_in[12];
    const float* b_ih_b     = (const float*)d_in[13];
    const float* b_hh_b     = (const float*)d_in[14];
    const float* emission_w = (const float*)d_in[15];
    const float* emission_b = (const float*)d_in[16];
    const float* sel_u_w    = (const float*)d_in[17];
    const float* sel_u_b    = (const float*)d_in[18];
    const float* sel_v_w    = (const float*)d_in[19];
    const float* sel_v_b    = (const float*)d_in[20];
    const float* sel_uv_w   = (const float*)d_in[21];
    const float* sel_uv_b   = (const float*)d_in[22];
    const float* crf_trans  = (const float*)d_in[23];
    const float* crf_start  = (const float*)d_in[24];
    const float* crf_end    = (const float*)d_in[25];

    // embed + bsum + accumulator zeroing in one launch
    prep_kernel<<<2417, 256>>>(tokens, word_emb,
                               b_ih_f, b_hh_f, b_ih_b, b_hh_b);

    // fused input projection for both directions
    xproj_gemm<<<dim3(64, 16), 256>>>(w_ih_f, w_ih_b);

    // persistent BiLSTM (40KB dynamic smem, flag-broadcast barrier)
    lstm_persist<<<128, 256, 40960>>>(w_hh_f, w_hh_b);

    // oc concat (float4) + emission (warp-per-row) in one launch
    oc_emi_kernel<<<1408, 256>>>(bio_gold, bio_emb, emission_w, emission_b);

    // u = relu(oc@u_w^T+b) and v = relu(oc@v_w^T+b) in one launch
    sgemm_nt2<<<dim3(2, 32, 2), 256>>>(OC_OFF, OC_OFF, 576,
                                       sel_u_w, sel_v_w, 576,
                                       U_OFF, V_OFF, NREL, 576,
                                       sel_u_b, sel_v_b, 1);
    // u1 = u@w1^T and v2 = v@w2^T in one launch
    sgemm_nt2<<<dim3(2, 32, 2), 256>>>(U_OFF, V_OFF, NREL,
                                       sel_uv_w, sel_uv_w + NREL, 2 * NREL,
                                       U1_OFF, V2_OFF, NREL, NREL,
                                       nullptr, nullptr, 0);

    // selection loss (1024 blocks) + CRF/mask-count (block 1024) overlapped
    sel_crf_kernel<<<1025, 160>>>(sel_gold, rel_emb, sel_uv_b,
                                  tokens, bio_gold,
                                  crf_trans, crf_start, crf_end);
    final_kernel<<<1, 1>>>((float*)d_out);
}